// round 15
// baseline (speedup 1.0000x reference)
#include <cuda_runtime.h>
#include <cuda_fp16.h>
#include <math.h>

// Problem constants
#define Bn   16
#define Nn   16
#define Hh   896
#define Ww   896
#define PH   300
#define PW   300
#define MINPH 60.0f

#define NPIX  (Hh*Ww)                        // 802816
#define NCELL (PH*PW)                        // 90000
#define IMG_ELEMS ((size_t)Bn*NPIX*3)        // 38,535,168

// Output layout: imgs_out [B,H,W,C], pboxes [B,N,4], valid [B,N], td [B,N,3], grads [PH,PW,C]
#define OFF_PBOX  (IMG_ELEMS)
#define OFF_VALID (OFF_PBOX + (size_t)1024)
#define OFF_TD    (OFF_VALID + (size_t)256)
#define OFF_GRADS (OFF_TD + (size_t)768)

// Mega-kernel block families
#define NGB        352                       // grads blocks (ceil(90000/256))
#define IMG_BX     7                         // Ww/128
#define IMG_BY     112                       // Hh/8
#define IMG_BLOCKS (IMG_BX*IMG_BY*Bn)        // 12544
#define NBLOCKS    (NGB + IMG_BLOCKS)

// Scratch (__device__ globals)
__device__ int4   g_boxi[Bn*Nn];     // {yp, xp, ph, pw}; 0 if invalid
__device__ float4 g_boxf[Bn*Nn];     // {inv_y, yp*inv_y+0.5, inv_x, xp*inv_x+0.5}
__device__ float  g_A[Bn*Nn*PH];     // row weight sums per box
__device__ float  g_Bw[Bn*Nn*PW];    // col weight sums per box
__device__ uint4  g_pph[NCELL];      // patch row-pair pack: rows r,r+1 RGB in half

// ---------------------------------------------------------------------------
// Kernel 1: fused _create + A/B vectors + small outputs + patch pair-pack.
// ---------------------------------------------------------------------------
__global__ void __launch_bounds__(320) k_init(const float* __restrict__ boxes,
                                              const int*   __restrict__ td,
                                              const float* __restrict__ patch,
                                              float* __restrict__ out)
{
    const int bn = blockIdx.x;

    for (int cell = bn * 320 + threadIdx.x; cell < NCELL; cell += 256*320) {
        int r = cell / PW;
        int c = cell - r * PW;
        int r1 = (r + 1 < PH) ? r + 1 : r;
        const float* p0 = patch + (size_t)cell * 3;
        const float* p1 = patch + ((size_t)r1 * PW + c) * 3;
        __half h[8];
        h[0] = __float2half_rn(p0[0]); h[1] = __float2half_rn(p0[1]);
        h[2] = __float2half_rn(p0[2]); h[3] = __float2half_rn(p1[0]);
        h[4] = __float2half_rn(p1[1]); h[5] = __float2half_rn(p1[2]);
        h[6] = __ushort_as_half(0);    h[7] = __ushort_as_half(0);
        g_pph[cell] = *(const uint4*)h;
    }

    float ymin = __ldg(boxes + bn*4+0);
    float xmin = __ldg(boxes + bn*4+1);
    float ymax = __ldg(boxes + bn*4+2);
    float xmax = __ldg(boxes + bn*4+3);

    float h  = ymax - ymin;
    float w  = xmax - xmin;
    float pwf = h * 0.5f;
    float phf = pwf;
    float oy = ymin + h * 0.5f;
    float ox = xmin + w * 0.5f;
    float yp = fmaxf(oy - phf * 0.5f, 0.0f);
    float xp = fmaxf(ox - pwf * 0.5f, 0.0f);
    if (yp + phf > (float)Hh) yp = (float)Hh - phf;
    if (xp + pwf > (float)Ww) xp = (float)Ww - pwf;

    bool valid = (phf > MINPH);

    int4 bi; float4 bf;
    if (!valid) {
        bi = make_int4(0,0,0,0);
        bf = make_float4(0.f,0.f,0.f,0.f);
    } else {
        int ypi = (int)yp, xpi = (int)xp;
        int phi = max((int)phf, 1);
        int pwi = max((int)pwf, 1);
        bi = make_int4(ypi, xpi, phi, pwi);
        float s0 = (float)phi / (float)PH;  float inv0 = 1.0f / s0;
        float s1 = (float)pwi / (float)PW;  float inv1 = 1.0f / s1;
        bf = make_float4(inv0, (float)ypi*inv0 + 0.5f,
                         inv1, (float)xpi*inv1 + 0.5f);
    }

    if (threadIdx.x == 0) {
        float* out_pb = out + OFF_PBOX;
        out_pb[bn*4+0] = yp; out_pb[bn*4+1] = xp;
        out_pb[bn*4+2] = phf; out_pb[bn*4+3] = pwf;
        out[OFF_VALID + bn] = valid ? 1.0f : 0.0f;
        #pragma unroll
        for (int k = 0; k < 3; ++k)
            out[OFF_TD + (size_t)bn*3 + k] = (__ldg(td + bn*3+k) != 0) ? 1.0f : 0.0f;
        g_boxi[bn] = bi;
        g_boxf[bn] = bf;
    }

    int p = threadIdx.x;
    if (p >= PH) return;
    float a = 0.0f, bb = 0.0f;
    if (bi.z > 0) {
        {
            float r = (float)bi.z / (float)PH;
            int k0 = (int)floorf(((float)p + 0.5f) * r - 0.5f) - 2;
            #pragma unroll
            for (int dk = 0; dk < 5; ++dk) {
                int k = k0 + dk;
                if (k < 0 || k >= bi.z) continue;
                float u = ((float)k + 0.5f) * bf.x - 0.5f;
                float wgt = 1.0f - fabsf(u - (float)p);
                if (wgt > 0.0f) a += wgt;
            }
        }
        {
            float r = (float)bi.w / (float)PW;
            int k0 = (int)floorf(((float)p + 0.5f) * r - 0.5f) - 2;
            #pragma unroll
            for (int dk = 0; dk < 5; ++dk) {
                int k = k0 + dk;
                if (k < 0 || k >= bi.w) continue;
                float u = ((float)k + 0.5f) * bf.z - 0.5f;
                float wgt = 1.0f - fabsf(u - (float)p);
                if (wgt > 0.0f) bb += wgt;
            }
        }
    }
    g_A [bn*PH + p] = a;
    g_Bw[bn*PW + p] = bb;
}

// ---------------------------------------------------------------------------
// Bilinear via 2 row-pair taps (full form, mixed path).
// ---------------------------------------------------------------------------
__device__ __forceinline__ void bil3h(float4 f, float fi, int jj, float* o)
{
    float u  = fi * f.x - f.y;
    float vv = ((float)jj + 0.5f) * f.z - f.w;
    float fu = floorf(u), fv = floorf(vv);
    float du = u - fu,    dv = vv - fv;
    int r0 = (int)fu, c0 = (int)fv;
    const uint4* pp = g_pph + (size_t)r0 * PW + c0;
    uint4 e0 = pp[0], e1 = pp[1];
    float2 A = __half22float2(*(const __half2*)&e0.x);
    float2 B = __half22float2(*(const __half2*)&e0.y);
    float2 C = __half22float2(*(const __half2*)&e0.z);
    float2 D = __half22float2(*(const __half2*)&e1.x);
    float2 E = __half22float2(*(const __half2*)&e1.y);
    float2 G = __half22float2(*(const __half2*)&e1.z);
    float w00 = (1.0f-du)*(1.0f-dv);
    float w01 = (1.0f-du)*dv;
    float w10 = du*(1.0f-dv);
    float w11 = du*dv;
    o[0] = w00*A.x + w01*D.x + w10*B.y + w11*E.y;
    o[1] = w00*A.y + w01*D.y + w10*C.x + w11*G.x;
    o[2] = w00*B.x + w01*E.x + w10*C.y + w11*G.y;
}

// Row-hoisted variant: prow = g_pph + r0*PW, du fixed per warp-row.
__device__ __forceinline__ void bil3h_row(const uint4* __restrict__ prow,
                                          float du, float omdu,
                                          float vv, float* o)
{
    float fv = floorf(vv);
    float dv = vv - fv;
    int   c0 = (int)fv;
    uint4 e0 = prow[c0], e1 = prow[c0+1];
    float2 A = __half22float2(*(const __half2*)&e0.x);
    float2 B = __half22float2(*(const __half2*)&e0.y);
    float2 C = __half22float2(*(const __half2*)&e0.z);
    float2 D = __half22float2(*(const __half2*)&e1.x);
    float2 E = __half22float2(*(const __half2*)&e1.y);
    float2 G = __half22float2(*(const __half2*)&e1.z);
    float w00 = omdu*(1.0f-dv);
    float w01 = omdu*dv;
    float w10 = du*(1.0f-dv);
    float w11 = du*dv;
    o[0] = w00*A.x + w01*D.x + w10*B.y + w11*E.y;
    o[1] = w00*A.y + w01*D.y + w10*C.x + w11*G.x;
    o[2] = w00*B.x + w01*E.x + w10*C.y + w11*G.y;
}

// ---------------------------------------------------------------------------
// Kernel 2 (mega): grads family + image family.
// ---------------------------------------------------------------------------
__global__ void __launch_bounds__(256) k_mega(const float* __restrict__ images,
                                              const float* __restrict__ hg,
                                              float* __restrict__ out)
{
    const int bid = blockIdx.x;
    const int t   = threadIdx.x;

    // ======================= family 1: grads ==============================
    if (bid < NGB) {
        const int base = bid * 256;
        const int idx  = base + t;             // p*PW + q
        const int p0   = base / PW;

        __shared__ float As[2][Bn*Nn];
        As[0][t] = g_A[t*PH + p0];
        As[1][t] = (p0 + 1 < PH) ? g_A[t*PH + p0 + 1] : 0.0f;
        __syncthreads();
        if (idx >= NCELL) return;

        const int p = idx / PW;
        const int q = idx - p * PW;
        const float* Arow = As[p - p0];

        float o0 = 0.f, o1 = 0.f, o2 = 0.f;
        #pragma unroll 4
        for (int b = 0; b < Bn; ++b) {
            float s = 0.f;
            #pragma unroll
            for (int n = 0; n < Nn; ++n)
                s += Arow[b*Nn + n] * g_Bw[(b*Nn + n)*PW + q];
            size_t hb = ((size_t)b * NCELL + idx) * 3;
            o0 += s * hg[hb+0];
            o1 += s * hg[hb+1];
            o2 += s * hg[hb+2];
        }
        float* outg = out + OFF_GRADS + (size_t)idx * 3;
        outg[0] = o0; outg[1] = o1; outg[2] = o2;
        return;
    }

    // ======================= family 2: image composite ====================
    {
        const int r    = bid - NGB;
        const int b    = r / (IMG_BX * IMG_BY);
        const int rem  = r - b * (IMG_BX * IMG_BY);
        const int by   = rem / IMG_BX;
        const int bx   = rem - by * IMG_BX;
        const int j0   = bx * 128;
        const int i    = by * 8 + (t >> 5);
        const int lane = t & 31;
        const int wid  = t >> 5;

        __shared__ int4   sbi[Nn];
        __shared__ float4 sbf[Nn];
        __shared__ float4 srow[8][96];     // per-warp row staging (mixed path)
        if (t < Nn) {
            sbi[t] = g_boxi[b*Nn + t];
            sbf[t] = g_boxf[b*Nn + t];
        }
        __syncthreads();

        bool inter = false;
        if (lane < Nn) {
            int4 bx4 = sbi[lane];
            inter = (bx4.z > 0) &&
                    ((unsigned)(i - bx4.x) < (unsigned)bx4.z) &&
                    (bx4.y < j0 + 128) && (bx4.y + bx4.w > j0);
        }
        unsigned mask = __ballot_sync(0xffffffffu, inter);

        size_t fbase = ((size_t)b * NPIX + (size_t)i * Ww + j0) * 3;
        const float4* src4 = (const float4*)(images + fbase);
        float4*       dst4 = (float4*)(out + fbase);

        if (mask == 0u) {
            dst4[lane     ] = src4[lane     ];
            dst4[lane + 32] = src4[lane + 32];
            dst4[lane + 64] = src4[lane + 64];
            return;
        }

        const float fi = (float)i + 0.5f;

        // O(1) uniform test: topmost intersecting box spans the whole row?
        {
            int  ntop = 31 - __clz(mask);
            int4 btop = sbi[ntop];
            if (btop.y <= j0 && btop.y + btop.w >= j0 + 128) {
                // uniform covered row: hoisted row math, direct stores
                float4 f = sbf[ntop];
                float u  = fi * f.x - f.y;
                float fu = floorf(u);
                float du = u - fu;
                float omdu = 1.0f - du;
                const uint4* prow = g_pph + (size_t)(int)fu * PW;
                #pragma unroll
                for (int s = 0; s < 4; ++s) {
                    int p = s*32 + lane;
                    float vv = ((float)(j0 + p) + 0.5f) * f.z - f.w;
                    float o[3];
                    bil3h_row(prow, du, omdu, vv, o);
                    size_t off = fbase + (size_t)p*3;
                    out[off+0] = o[0];
                    out[off+1] = o[1];
                    out[off+2] = o[2];
                }
                return;
            }
        }

        // per-pixel top-box hits, pixel-major
        int hit[4];
        unsigned covw[4];
        #pragma unroll
        for (int s = 0; s < 4; ++s) {
            int j = j0 + s*32 + lane;
            int h = -1;
            unsigned m = mask;
            while (m) {
                int n = 31 - __clz(m);
                int4 bx4 = sbi[n];
                if ((unsigned)(j - bx4.y) < (unsigned)bx4.w) { h = n; break; }
                m &= ~(1u << n);
            }
            hit[s] = h;
            covw[s] = __ballot_sync(0xffffffffu, h >= 0);
        }

        // ---- mixed warp: smem reassembly path ----
        float4* my4 = srow[wid];
        float*  myf = (float*)my4;

        #pragma unroll
        for (int rr = 0; rr < 3; ++rr) {
            int l4 = lane + rr*32;
            int pa = (l4*4)/3;
            int pb = pa + 1;
            unsigned ca = (covw[pa>>5] >> (pa&31)) & 1u;
            unsigned cb = (covw[pb>>5] >> (pb&31)) & 1u;
            if (!(ca & cb))
                my4[l4] = src4[l4];
        }
        __syncwarp();

        #pragma unroll
        for (int s = 0; s < 4; ++s) {
            if (hit[s] >= 0) {
                int p = s*32 + lane;
                float o[3];
                bil3h(sbf[hit[s]], fi, j0 + p, o);
                myf[p*3+0] = o[0];
                myf[p*3+1] = o[1];
                myf[p*3+2] = o[2];
            }
        }
        __syncwarp();

        #pragma unroll
        for (int rr = 0; rr < 3; ++rr) {
            int l4 = lane + rr*32;
            dst4[l4] = my4[l4];
        }
    }
}

// ---------------------------------------------------------------------------
extern "C" void kernel_launch(void* const* d_in, const int* in_sizes, int n_in,
                              void* d_out, int out_size)
{
    const float* boxes  = (const float*)d_in[0];
    const float* images = (const float*)d_in[1];
    const float* patch  = (const float*)d_in[2];
    const float* hg     = (const float*)d_in[3];
    const int*   td     = (const int*)  d_in[4];
    float* out = (float*)d_out;

    k_init<<<Bn*Nn, 320>>>(boxes, td, patch, out);
    k_mega<<<NBLOCKS, 256>>>(images, hg, out);
}

// round 16
// speedup vs baseline: 1.0328x; 1.0328x over previous
#include <cuda_runtime.h>
#include <cuda_fp16.h>
#include <math.h>

// Problem constants
#define Bn   16
#define Nn   16
#define Hh   896
#define Ww   896
#define PH   300
#define PW   300
#define MINPH 60.0f

#define NPIX  (Hh*Ww)                        // 802816
#define NCELL (PH*PW)                        // 90000
#define IMG_ELEMS ((size_t)Bn*NPIX*3)        // 38,535,168

// Output layout: imgs_out [B,H,W,C], pboxes [B,N,4], valid [B,N], td [B,N,3], grads [PH,PW,C]
#define OFF_PBOX  (IMG_ELEMS)
#define OFF_VALID (OFF_PBOX + (size_t)1024)
#define OFF_TD    (OFF_VALID + (size_t)256)
#define OFF_GRADS (OFF_TD + (size_t)768)

// Mega-kernel block families
#define NGB        352                       // grads blocks (ceil(90000/256))
#define IMG_BX     7                         // Ww/128
#define IMG_BY     56                        // Hh/16 (16 rows per block)
#define IMG_BLOCKS (IMG_BX*IMG_BY*Bn)        // 6272
#define NBLOCKS    (NGB + IMG_BLOCKS)        // 6624

// Scratch (__device__ globals)
__device__ int4   g_boxi[Bn*Nn];     // {yp, xp, ph, pw}; 0 if invalid
__device__ float4 g_boxf[Bn*Nn];     // {inv_y, yp*inv_y+0.5, inv_x, xp*inv_x+0.5}
__device__ float  g_A[Bn*Nn*PH];     // row weight sums per box
__device__ float  g_Bw[Bn*Nn*PW];    // col weight sums per box
__device__ uint4  g_pph[NCELL];      // patch row-pair pack: rows r,r+1 RGB in half

// ---------------------------------------------------------------------------
// Kernel 1: fused _create + A/B vectors + small outputs + patch pair-pack.
// ---------------------------------------------------------------------------
__global__ void __launch_bounds__(320) k_init(const float* __restrict__ boxes,
                                              const int*   __restrict__ td,
                                              const float* __restrict__ patch,
                                              float* __restrict__ out)
{
    const int bn = blockIdx.x;

    for (int cell = bn * 320 + threadIdx.x; cell < NCELL; cell += 256*320) {
        int r = cell / PW;
        int c = cell - r * PW;
        int r1 = (r + 1 < PH) ? r + 1 : r;
        const float* p0 = patch + (size_t)cell * 3;
        const float* p1 = patch + ((size_t)r1 * PW + c) * 3;
        __half h[8];
        h[0] = __float2half_rn(p0[0]); h[1] = __float2half_rn(p0[1]);
        h[2] = __float2half_rn(p0[2]); h[3] = __float2half_rn(p1[0]);
        h[4] = __float2half_rn(p1[1]); h[5] = __float2half_rn(p1[2]);
        h[6] = __ushort_as_half(0);    h[7] = __ushort_as_half(0);
        g_pph[cell] = *(const uint4*)h;
    }

    float ymin = __ldg(boxes + bn*4+0);
    float xmin = __ldg(boxes + bn*4+1);
    float ymax = __ldg(boxes + bn*4+2);
    float xmax = __ldg(boxes + bn*4+3);

    float h  = ymax - ymin;
    float w  = xmax - xmin;
    float pwf = h * 0.5f;
    float phf = pwf;
    float oy = ymin + h * 0.5f;
    float ox = xmin + w * 0.5f;
    float yp = fmaxf(oy - phf * 0.5f, 0.0f);
    float xp = fmaxf(ox - pwf * 0.5f, 0.0f);
    if (yp + phf > (float)Hh) yp = (float)Hh - phf;
    if (xp + pwf > (float)Ww) xp = (float)Ww - pwf;

    bool valid = (phf > MINPH);

    int4 bi; float4 bf;
    if (!valid) {
        bi = make_int4(0,0,0,0);
        bf = make_float4(0.f,0.f,0.f,0.f);
    } else {
        int ypi = (int)yp, xpi = (int)xp;
        int phi = max((int)phf, 1);
        int pwi = max((int)pwf, 1);
        bi = make_int4(ypi, xpi, phi, pwi);
        float s0 = (float)phi / (float)PH;  float inv0 = 1.0f / s0;
        float s1 = (float)pwi / (float)PW;  float inv1 = 1.0f / s1;
        bf = make_float4(inv0, (float)ypi*inv0 + 0.5f,
                         inv1, (float)xpi*inv1 + 0.5f);
    }

    if (threadIdx.x == 0) {
        float* out_pb = out + OFF_PBOX;
        out_pb[bn*4+0] = yp; out_pb[bn*4+1] = xp;
        out_pb[bn*4+2] = phf; out_pb[bn*4+3] = pwf;
        out[OFF_VALID + bn] = valid ? 1.0f : 0.0f;
        #pragma unroll
        for (int k = 0; k < 3; ++k)
            out[OFF_TD + (size_t)bn*3 + k] = (__ldg(td + bn*3+k) != 0) ? 1.0f : 0.0f;
        g_boxi[bn] = bi;
        g_boxf[bn] = bf;
    }

    int p = threadIdx.x;
    if (p >= PH) return;
    float a = 0.0f, bb = 0.0f;
    if (bi.z > 0) {
        {
            float r = (float)bi.z / (float)PH;
            int k0 = (int)floorf(((float)p + 0.5f) * r - 0.5f) - 2;
            #pragma unroll
            for (int dk = 0; dk < 5; ++dk) {
                int k = k0 + dk;
                if (k < 0 || k >= bi.z) continue;
                float u = ((float)k + 0.5f) * bf.x - 0.5f;
                float wgt = 1.0f - fabsf(u - (float)p);
                if (wgt > 0.0f) a += wgt;
            }
        }
        {
            float r = (float)bi.w / (float)PW;
            int k0 = (int)floorf(((float)p + 0.5f) * r - 0.5f) - 2;
            #pragma unroll
            for (int dk = 0; dk < 5; ++dk) {
                int k = k0 + dk;
                if (k < 0 || k >= bi.w) continue;
                float u = ((float)k + 0.5f) * bf.z - 0.5f;
                float wgt = 1.0f - fabsf(u - (float)p);
                if (wgt > 0.0f) bb += wgt;
            }
        }
    }
    g_A [bn*PH + p] = a;
    g_Bw[bn*PW + p] = bb;
}

// ---------------------------------------------------------------------------
// Bilinear via 2 row-pair taps (full form, mixed path).
// ---------------------------------------------------------------------------
__device__ __forceinline__ void bil3h(float4 f, float fi, int jj, float* o)
{
    float u  = fi * f.x - f.y;
    float vv = ((float)jj + 0.5f) * f.z - f.w;
    float fu = floorf(u), fv = floorf(vv);
    float du = u - fu,    dv = vv - fv;
    int r0 = (int)fu, c0 = (int)fv;
    const uint4* pp = g_pph + (size_t)r0 * PW + c0;
    uint4 e0 = pp[0], e1 = pp[1];
    float2 A = __half22float2(*(const __half2*)&e0.x);
    float2 B = __half22float2(*(const __half2*)&e0.y);
    float2 C = __half22float2(*(const __half2*)&e0.z);
    float2 D = __half22float2(*(const __half2*)&e1.x);
    float2 E = __half22float2(*(const __half2*)&e1.y);
    float2 G = __half22float2(*(const __half2*)&e1.z);
    float w00 = (1.0f-du)*(1.0f-dv);
    float w01 = (1.0f-du)*dv;
    float w10 = du*(1.0f-dv);
    float w11 = du*dv;
    o[0] = w00*A.x + w01*D.x + w10*B.y + w11*E.y;
    o[1] = w00*A.y + w01*D.y + w10*C.x + w11*G.x;
    o[2] = w00*B.x + w01*E.x + w10*C.y + w11*G.y;
}

// Row-hoisted variant for uniform rows.
__device__ __forceinline__ void bil3h_row(const uint4* __restrict__ prow,
                                          float du, float omdu,
                                          float vv, float* o)
{
    float fv = floorf(vv);
    float dv = vv - fv;
    int   c0 = (int)fv;
    uint4 e0 = prow[c0], e1 = prow[c0+1];
    float2 A = __half22float2(*(const __half2*)&e0.x);
    float2 B = __half22float2(*(const __half2*)&e0.y);
    float2 C = __half22float2(*(const __half2*)&e0.z);
    float2 D = __half22float2(*(const __half2*)&e1.x);
    float2 E = __half22float2(*(const __half2*)&e1.y);
    float2 G = __half22float2(*(const __half2*)&e1.z);
    float w00 = omdu*(1.0f-dv);
    float w01 = omdu*dv;
    float w10 = du*(1.0f-dv);
    float w11 = du*dv;
    o[0] = w00*A.x + w01*D.x + w10*B.y + w11*E.y;
    o[1] = w00*A.y + w01*D.y + w10*C.x + w11*G.x;
    o[2] = w00*B.x + w01*E.x + w10*C.y + w11*G.y;
}

// ---------------------------------------------------------------------------
// One covered/mixed row (mask != 0). Proven R14/R15 logic.
// ---------------------------------------------------------------------------
__device__ __forceinline__ void do_row(unsigned mask, int i, int j0,
                                       size_t fbase, int lane,
                                       const int4* __restrict__ sbi,
                                       const float4* __restrict__ sbf,
                                       float4* __restrict__ my4,
                                       const float* __restrict__ images,
                                       float* __restrict__ out)
{
    const float4* src4 = (const float4*)(images + fbase);
    float4*       dst4 = (float4*)(out + fbase);
    const float fi = (float)i + 0.5f;

    // O(1) uniform test: topmost intersecting box spans the whole row?
    {
        int  ntop = 31 - __clz(mask);
        int4 btop = sbi[ntop];
        if (btop.y <= j0 && btop.y + btop.w >= j0 + 128) {
            float4 f = sbf[ntop];
            float u  = fi * f.x - f.y;
            float fu = floorf(u);
            float du = u - fu;
            float omdu = 1.0f - du;
            const uint4* prow = g_pph + (size_t)(int)fu * PW;
            #pragma unroll
            for (int s = 0; s < 4; ++s) {
                int p = s*32 + lane;
                float vv = ((float)(j0 + p) + 0.5f) * f.z - f.w;
                float o[3];
                bil3h_row(prow, du, omdu, vv, o);
                size_t off = fbase + (size_t)p*3;
                out[off+0] = o[0];
                out[off+1] = o[1];
                out[off+2] = o[2];
            }
            return;
        }
    }

    // per-pixel top-box hits, pixel-major
    int hit[4];
    unsigned covw[4];
    #pragma unroll
    for (int s = 0; s < 4; ++s) {
        int j = j0 + s*32 + lane;
        int h = -1;
        unsigned m = mask;
        while (m) {
            int n = 31 - __clz(m);
            int4 bx4 = sbi[n];
            if ((unsigned)(j - bx4.y) < (unsigned)bx4.w) { h = n; break; }
            m &= ~(1u << n);
        }
        hit[s] = h;
        covw[s] = __ballot_sync(0xffffffffu, h >= 0);
    }

    float* myf = (float*)my4;

    #pragma unroll
    for (int rr = 0; rr < 3; ++rr) {
        int l4 = lane + rr*32;
        int pa = (l4*4)/3;
        int pb = pa + 1;
        unsigned ca = (covw[pa>>5] >> (pa&31)) & 1u;
        unsigned cb = (covw[pb>>5] >> (pb&31)) & 1u;
        if (!(ca & cb))
            my4[l4] = src4[l4];
    }
    __syncwarp();

    #pragma unroll
    for (int s = 0; s < 4; ++s) {
        if (hit[s] >= 0) {
            int p = s*32 + lane;
            float o[3];
            bil3h(sbf[hit[s]], fi, j0 + p, o);
            myf[p*3+0] = o[0];
            myf[p*3+1] = o[1];
            myf[p*3+2] = o[2];
        }
    }
    __syncwarp();

    #pragma unroll
    for (int rr = 0; rr < 3; ++rr) {
        int l4 = lane + rr*32;
        dst4[l4] = my4[l4];
    }
    __syncwarp();
}

// ---------------------------------------------------------------------------
// Kernel 2 (mega): grads family + image family (2 rows per warp).
// ---------------------------------------------------------------------------
__global__ void __launch_bounds__(256) k_mega(const float* __restrict__ images,
                                              const float* __restrict__ hg,
                                              float* __restrict__ out)
{
    const int bid = blockIdx.x;
    const int t   = threadIdx.x;

    // ======================= family 1: grads ==============================
    if (bid < NGB) {
        const int base = bid * 256;
        const int idx  = base + t;             // p*PW + q
        const int p0   = base / PW;

        __shared__ float As[2][Bn*Nn];
        As[0][t] = g_A[t*PH + p0];
        As[1][t] = (p0 + 1 < PH) ? g_A[t*PH + p0 + 1] : 0.0f;
        __syncthreads();
        if (idx >= NCELL) return;

        const int p = idx / PW;
        const int q = idx - p * PW;
        const float* Arow = As[p - p0];

        float o0 = 0.f, o1 = 0.f, o2 = 0.f;
        #pragma unroll 4
        for (int b = 0; b < Bn; ++b) {
            float s = 0.f;
            #pragma unroll
            for (int n = 0; n < Nn; ++n)
                s += Arow[b*Nn + n] * g_Bw[(b*Nn + n)*PW + q];
            size_t hb = ((size_t)b * NCELL + idx) * 3;
            o0 += s * hg[hb+0];
            o1 += s * hg[hb+1];
            o2 += s * hg[hb+2];
        }
        float* outg = out + OFF_GRADS + (size_t)idx * 3;
        outg[0] = o0; outg[1] = o1; outg[2] = o2;
        return;
    }

    // ======================= family 2: image composite ====================
    {
        const int r    = bid - NGB;
        const int b    = r / (IMG_BX * IMG_BY);
        const int rem  = r - b * (IMG_BX * IMG_BY);
        const int by   = rem / IMG_BX;
        const int bx   = rem - by * IMG_BX;
        const int j0   = bx * 128;
        const int lane = t & 31;
        const int wid  = t >> 5;
        const int i0   = by * 16 + wid * 2;    // rows i0, i0+1

        __shared__ int4   sbi[Nn];
        __shared__ float4 sbf[Nn];
        __shared__ float4 srow[8][96];
        if (t < Nn) {
            sbi[t] = g_boxi[b*Nn + t];
            sbf[t] = g_boxf[b*Nn + t];
        }
        __syncthreads();

        bool in0 = false, in1 = false;
        if (lane < Nn) {
            int4 bx4 = sbi[lane];
            bool colov = (bx4.z > 0) && (bx4.y < j0 + 128) && (bx4.y + bx4.w > j0);
            in0 = colov && ((unsigned)(i0     - bx4.x) < (unsigned)bx4.z);
            in1 = colov && ((unsigned)(i0 + 1 - bx4.x) < (unsigned)bx4.z);
        }
        unsigned mask0 = __ballot_sync(0xffffffffu, in0);
        unsigned mask1 = __ballot_sync(0xffffffffu, in1);

        size_t fbase0 = ((size_t)b * NPIX + (size_t)i0 * Ww + j0) * 3;
        size_t fbase1 = fbase0 + (size_t)Ww * 3;

        if ((mask0 | mask1) == 0u) {
            // both rows miss: 6 independent loads, then 6 stores (2x MLP)
            const float4* s0 = (const float4*)(images + fbase0);
            const float4* s1 = (const float4*)(images + fbase1);
            float4*       d0 = (float4*)(out + fbase0);
            float4*       d1 = (float4*)(out + fbase1);
            float4 a0 = s0[lane], a1 = s0[lane+32], a2 = s0[lane+64];
            float4 b0 = s1[lane], b1 = s1[lane+32], b2 = s1[lane+64];
            d0[lane]    = a0; d0[lane+32] = a1; d0[lane+64] = a2;
            d1[lane]    = b0; d1[lane+32] = b1; d1[lane+64] = b2;
            return;
        }

        // row 0
        if (mask0 == 0u) {
            const float4* s0 = (const float4*)(images + fbase0);
            float4*       d0 = (float4*)(out + fbase0);
            d0[lane]    = s0[lane];
            d0[lane+32] = s0[lane+32];
            d0[lane+64] = s0[lane+64];
        } else {
            do_row(mask0, i0, j0, fbase0, lane, sbi, sbf, srow[wid], images, out);
        }
        // row 1
        if (mask1 == 0u) {
            const float4* s1 = (const float4*)(images + fbase1);
            float4*       d1 = (float4*)(out + fbase1);
            d1[lane]    = s1[lane];
            d1[lane+32] = s1[lane+32];
            d1[lane+64] = s1[lane+64];
        } else {
            do_row(mask1, i0 + 1, j0, fbase1, lane, sbi, sbf, srow[wid], images, out);
        }
    }
}

// ---------------------------------------------------------------------------
extern "C" void kernel_launch(void* const* d_in, const int* in_sizes, int n_in,
                              void* d_out, int out_size)
{
    const float* boxes  = (const float*)d_in[0];
    const float* images = (const float*)d_in[1];
    const float* patch  = (const float*)d_in[2];
    const float* hg     = (const float*)d_in[3];
    const int*   td     = (const int*)  d_in[4];
    float* out = (float*)d_out;

    k_init<<<Bn*Nn, 320>>>(boxes, td, patch, out);
    k_mega<<<NBLOCKS, 256>>>(images, hg, out);
}